// round 1
// baseline (speedup 1.0000x reference)
#include <cuda_runtime.h>
#include <math.h>

#define TT 128
#define NB 256
#define EE 512
#define AD 8
#define HH 512
#define H3 1536
#define TN (TT*NB)
#define TNH (TN*HH)
#define NH (NB*HH)

// Scratch (no cudaMalloc allowed)
__device__ float g_gi [(size_t)TN * H3];   // input-side gates, cell 1
__device__ float g_gip[(size_t)TN * H3];   // input-side gates, cell 2
__device__ float g_gh [NB * 2 * H3];       // recurrent gates, both cells (ldc=3072)
__device__ float g_A1 [NB * HH];           // masked hidden, cell 1 (GEMM A operand)
__device__ float g_A2 [NB * HH];           // masked hidden, cell 2

__device__ __forceinline__ unsigned f2tf(float x) {
    unsigned r;
    asm("cvt.rna.tf32.f32 %0, %1;" : "=r"(r) : "f"(x));
    return r;
}

__device__ __forceinline__ void mma8(float* c, const unsigned* a, const unsigned* b) {
    asm volatile(
        "mma.sync.aligned.m16n8k8.row.col.f32.tf32.tf32.f32 "
        "{%0,%1,%2,%3},{%4,%5,%6,%7},{%8,%9},{%0,%1,%2,%3};"
        : "+f"(c[0]), "+f"(c[1]), "+f"(c[2]), "+f"(c[3])
        : "r"(a[0]), "r"(a[1]), "r"(a[2]), "r"(a[3]), "r"(b[0]), "r"(b[1]));
}

__device__ __forceinline__ float fsig(float x) {
    return 1.f / (1.f + __expf(-x));
}
__device__ __forceinline__ float ftanh(float x) {
    // accurate regardless of fast-math flags; __expf rel err ~1e-6
    return 1.f - 2.f / (__expf(2.f * x) + 1.f);
}

// MODE 0: gi GEMM  C(32768x1536) = x(32768x512) @ w_ih[:, :512]^T, plus a tail
//         k-chunk for the masked-action columns, plus gi_p (K=8) into acc2.
// MODE 1: step GEMM C(256x3072) = [A1|A2](256x512) @ [w_hh|w_hh_p]^T
template<int MODE, int BM, int BN, int WRM, int WRN>
__global__ void __launch_bounds__(256) gemm_k(
    const float* __restrict__ Aext,
    const float* __restrict__ B1, const float* __restrict__ B2,
    const float* __restrict__ pah, const float* __restrict__ masks,
    const float* __restrict__ bih, const float* __restrict__ bihp,
    const float* __restrict__ wihp)
{
    constexpr int BK = 16, SA = 20;
    constexpr int MT = BM / (WRM * 16);
    constexpr int NT = BN / (WRN * 8);
    constexpr int AV = BM * BK / 4 / 256;
    constexpr int BV = BN * BK / 4 / 256;
    constexpr int K = 512;

    __shared__ unsigned sA[2][BM * SA];
    __shared__ unsigned sB[2][BN * SA];

    const int m0 = blockIdx.y * BM;
    const float* Ag;
    const float* Bg;
    int n0, lda, ldb, ldc;
    float* C;
    if (MODE == 0) {
        Ag = Aext;
        Bg = B1 + (size_t)blockIdx.x * BN * 520;
        n0 = blockIdx.x * BN; lda = EE; ldb = 520; ldc = H3; C = g_gi;
    } else {
        constexpr int NPC = H3 / BN;
        const int cell = blockIdx.x >= NPC;
        Ag = cell ? g_A2 : g_A1;
        Bg = cell ? (B2 + (size_t)(blockIdx.x - NPC) * BN * HH)
                  : (B1 + (size_t)blockIdx.x * BN * HH);
        n0 = blockIdx.x * BN; lda = HH; ldb = HH; ldc = 2 * H3; C = g_gh;
    }
    const int tid = threadIdx.x, lane = tid & 31, warp = tid >> 5;
    const int wm = warp % WRM, wn = warp / WRM;

    float acc[MT][NT][4];
    float acc2[MT][NT][4];
#pragma unroll
    for (int i = 0; i < MT; i++)
#pragma unroll
        for (int j = 0; j < NT; j++)
#pragma unroll
            for (int q = 0; q < 4; q++) {
                acc[i][j][q] = 0.f;
                if (MODE == 0) acc2[i][j][q] = 0.f;
            }

    unsigned ra[AV][4], rb[BV][4];

    auto GL = [&](int kc) {
#pragma unroll
        for (int i = 0; i < AV; i++) {
            int s = tid + i * 256; int r = s >> 2; int c = (s & 3) << 2;
            float4 v = *reinterpret_cast<const float4*>(Ag + (size_t)(m0 + r) * lda + kc * BK + c);
            ra[i][0] = f2tf(v.x); ra[i][1] = f2tf(v.y); ra[i][2] = f2tf(v.z); ra[i][3] = f2tf(v.w);
        }
#pragma unroll
        for (int i = 0; i < BV; i++) {
            int s = tid + i * 256; int r = s >> 2; int c = (s & 3) << 2;
            float4 v = *reinterpret_cast<const float4*>(Bg + (size_t)r * ldb + kc * BK + c);
            rb[i][0] = f2tf(v.x); rb[i][1] = f2tf(v.y); rb[i][2] = f2tf(v.z); rb[i][3] = f2tf(v.w);
        }
    };
    auto SS = [&](int buf) {
#pragma unroll
        for (int i = 0; i < AV; i++) {
            int s = tid + i * 256; int r = s >> 2; int c = (s & 3) << 2;
            *reinterpret_cast<uint4*>(&sA[buf][r * SA + c]) = *reinterpret_cast<uint4*>(ra[i]);
        }
#pragma unroll
        for (int i = 0; i < BV; i++) {
            int s = tid + i * 256; int r = s >> 2; int c = (s & 3) << 2;
            *reinterpret_cast<uint4*>(&sB[buf][r * SA + c]) = *reinterpret_cast<uint4*>(rb[i]);
        }
    };
    auto COMP = [&](int buf) {
#pragma unroll
        for (int k8 = 0; k8 < BK / 8; k8++) {
            unsigned af[MT][4]; unsigned bf[NT][2];
#pragma unroll
            for (int mt = 0; mt < MT; mt++) {
                int r = wm * MT * 16 + mt * 16 + (lane >> 2);
                int c = k8 * 8 + (lane & 3);
                af[mt][0] = sA[buf][r * SA + c];
                af[mt][1] = sA[buf][(r + 8) * SA + c];
                af[mt][2] = sA[buf][r * SA + c + 4];
                af[mt][3] = sA[buf][(r + 8) * SA + c + 4];
            }
#pragma unroll
            for (int nt = 0; nt < NT; nt++) {
                int n = wn * NT * 8 + nt * 8 + (lane >> 2);
                int kk = k8 * 8 + (lane & 3);
                bf[nt][0] = sB[buf][n * SA + kk];
                bf[nt][1] = sB[buf][n * SA + kk + 4];
            }
#pragma unroll
            for (int mt = 0; mt < MT; mt++)
#pragma unroll
                for (int nt = 0; nt < NT; nt++)
                    mma8(acc[mt][nt], af[mt], bf[nt]);
        }
    };

    GL(0); SS(0); __syncthreads();
    constexpr int NKC = K / BK;
    for (int kc = 0; kc < NKC; kc++) {
        if (kc + 1 < NKC) GL(kc + 1);
        COMP(kc & 1);
        if (kc + 1 < NKC) SS((kc + 1) & 1);
        __syncthreads();
    }

    if (MODE == 0) {
        // tail chunk: masked prev-action (K=8) vs w_ih[:,512:520] into acc,
        // and vs w_ih_p into acc2 (gi_p)
        {
            int s = tid;
            if (s < BM * 2) {
                int r = s >> 1; int c = (s & 1) << 2;
                float4 v = *reinterpret_cast<const float4*>(pah + (size_t)(m0 + r) * AD + c);
                float mk = masks[m0 + r];
                uint4 t4 = { f2tf(v.x * mk), f2tf(v.y * mk), f2tf(v.z * mk), f2tf(v.w * mk) };
                *reinterpret_cast<uint4*>(&sA[0][r * SA + c]) = t4;
            }
        }
        {
            int s = tid;
            if (s < BN * 2) {
                int n = s >> 1; int c = (s & 1) << 2;
                float4 v = *reinterpret_cast<const float4*>(B1 + (size_t)(n0 + n) * 520 + 512 + c);
                uint4 t4 = { f2tf(v.x), f2tf(v.y), f2tf(v.z), f2tf(v.w) };
                *reinterpret_cast<uint4*>(&sB[0][n * SA + c]) = t4;
                float4 w = *reinterpret_cast<const float4*>(wihp + (size_t)(n0 + n) * AD + c);
                uint4 t5 = { f2tf(w.x), f2tf(w.y), f2tf(w.z), f2tf(w.w) };
                *reinterpret_cast<uint4*>(&sB[1][n * SA + c]) = t5;
            }
        }
        __syncthreads();
        unsigned af2[MT][4], b0f[NT][2], b1f[NT][2];
#pragma unroll
        for (int mt = 0; mt < MT; mt++) {
            int r = wm * MT * 16 + mt * 16 + (lane >> 2);
            int c = (lane & 3);
            af2[mt][0] = sA[0][r * SA + c];
            af2[mt][1] = sA[0][(r + 8) * SA + c];
            af2[mt][2] = sA[0][r * SA + c + 4];
            af2[mt][3] = sA[0][(r + 8) * SA + c + 4];
        }
#pragma unroll
        for (int nt = 0; nt < NT; nt++) {
            int n = wn * NT * 8 + nt * 8 + (lane >> 2);
            int kk = (lane & 3);
            b0f[nt][0] = sB[0][n * SA + kk]; b0f[nt][1] = sB[0][n * SA + kk + 4];
            b1f[nt][0] = sB[1][n * SA + kk]; b1f[nt][1] = sB[1][n * SA + kk + 4];
        }
#pragma unroll
        for (int mt = 0; mt < MT; mt++)
#pragma unroll
            for (int nt = 0; nt < NT; nt++) {
                mma8(acc[mt][nt], af2[mt], b0f[nt]);
                mma8(acc2[mt][nt], af2[mt], b1f[nt]);
            }
    }

    // epilogue
#pragma unroll
    for (int mt = 0; mt < MT; mt++)
#pragma unroll
        for (int nt = 0; nt < NT; nt++) {
            int r = m0 + wm * MT * 16 + mt * 16 + (lane >> 2);
            int c = n0 + wn * NT * 8 + nt * 8 + ((lane & 3) << 1);
            if (MODE == 1) {
                *reinterpret_cast<float2*>(&C[(size_t)r * ldc + c]) =
                    make_float2(acc[mt][nt][0], acc[mt][nt][1]);
                *reinterpret_cast<float2*>(&C[(size_t)(r + 8) * ldc + c]) =
                    make_float2(acc[mt][nt][2], acc[mt][nt][3]);
            } else {
                float b0 = bih[c], b1 = bih[c + 1];
                *reinterpret_cast<float2*>(&g_gi[(size_t)r * H3 + c]) =
                    make_float2(acc[mt][nt][0] + b0, acc[mt][nt][1] + b1);
                *reinterpret_cast<float2*>(&g_gi[(size_t)(r + 8) * H3 + c]) =
                    make_float2(acc[mt][nt][2] + b0, acc[mt][nt][3] + b1);
                float p0 = bihp[c], p1 = bihp[c + 1];
                *reinterpret_cast<float2*>(&g_gip[(size_t)r * H3 + c]) =
                    make_float2(acc2[mt][nt][0] + p0, acc2[mt][nt][1] + p1);
                *reinterpret_cast<float2*>(&g_gip[(size_t)(r + 8) * H3 + c]) =
                    make_float2(acc2[mt][nt][2] + p0, acc2[mt][nt][3] + p1);
            }
        }
}

__global__ void init_k(const float* __restrict__ hxs, const float* __restrict__ hys,
                       const float* __restrict__ masks, const float* __restrict__ ginit)
{
    int idx = blockIdx.x * blockDim.x + threadIdx.x;
    int cell = idx >> 17;
    int e = idx & (NH - 1);
    int n = e >> 9;
    float m0 = masks[n];
    if (!cell) g_A1[e] = hxs[e] * m0;
    else       g_A2[e] = hys[e] * m0 + ginit[e] * (1.f - m0);
}

__global__ void gate_k(int t, const float* __restrict__ masks,
                       const float* __restrict__ ginit,
                       const float* __restrict__ bhh, const float* __restrict__ bhhp,
                       float* __restrict__ out)
{
    int idx = blockIdx.x * blockDim.x + threadIdx.x;
    int cell = idx >> 17;
    int e = idx & (NH - 1);
    int n = e >> 9, j = e & (HH - 1);
    size_t m = (size_t)t * NB + n;

    const float* gi = cell ? g_gip : g_gi;
    const float* bh = cell ? bhhp : bhh;
    float* Ab = cell ? g_A2 : g_A1;

    size_t gio = m * H3;
    float ir = gi[gio + j], iz = gi[gio + HH + j], inn = gi[gio + 2 * HH + j];
    size_t gho = (size_t)n * (2 * H3) + (size_t)cell * H3;
    float hr = g_gh[gho + j] + bh[j];
    float hz = g_gh[gho + HH + j] + bh[HH + j];
    float hn = g_gh[gho + 2 * HH + j] + bh[2 * HH + j];

    float r = fsig(ir + hr);
    float z = fsig(iz + hz);
    float nn = ftanh(inn + r * hn);
    float hp = Ab[e];
    float h = (1.f - z) * nn + z * hp;

    float* outs = out + (cell ? ((size_t)TNH + NH) : 0);
    outs[m * HH + j] = h;

    if (t == TT - 1) {
        float* hf = out + (cell ? (2 * (size_t)TNH + NH) : (size_t)TNH);
        hf[(size_t)n * HH + j] = h;
    } else {
        float mnx = masks[(size_t)(t + 1) * NB + n];
        float an = h * mnx;
        if (cell) an += ginit[((size_t)(t + 1) * NB + n) * HH + j] * (1.f - mnx);
        Ab[e] = an;
    }
}

extern "C" void kernel_launch(void* const* d_in, const int* in_sizes, int n_in,
                              void* d_out, int out_size)
{
    const float* x     = (const float*)d_in[0];
    const float* hxs   = (const float*)d_in[1];
    const float* hys   = (const float*)d_in[2];
    const float* ginit = (const float*)d_in[3];
    const float* masks = (const float*)d_in[4];
    const float* pah   = (const float*)d_in[5];
    const float* wih   = (const float*)d_in[6];
    const float* whh   = (const float*)d_in[7];
    const float* bih   = (const float*)d_in[8];
    const float* bhh   = (const float*)d_in[9];
    const float* wihp  = (const float*)d_in[10];
    const float* whhp  = (const float*)d_in[11];
    const float* bihp  = (const float*)d_in[12];
    const float* bhhp  = (const float*)d_in[13];
    float* out = (float*)d_out;

    init_k<<<1024, 256>>>(hxs, hys, masks, ginit);

    // gi = [x, ma] @ w_ih^T + b_ih ; gi_p = ma @ w_ih_p^T + b_ih_p
    gemm_k<0, 128, 128, 2, 4><<<dim3(12, 256), 256>>>(
        x, wih, nullptr, pah, masks, bih, bihp, wihp);

    for (int t = 0; t < TT; t++) {
        // gh = [A1|A2] @ [w_hh|w_hh_p]^T  (256 x 3072)
        gemm_k<1, 128, 64, 4, 2><<<dim3(48, 2), 256>>>(
            nullptr, whh, whhp, nullptr, nullptr, nullptr, nullptr, nullptr);
        // gates + hidden update + masked A-buffers for step t+1
        gate_k<<<1024, 256>>>(t, masks, ginit, bhh, bhhp, out);
    }
}

// round 2
// speedup vs baseline: 1.0872x; 1.0872x over previous
#include <cuda_runtime.h>
#include <math.h>

#define TT 128
#define NB 256
#define EE 512
#define AD 8
#define HH 512
#define H3 1536
#define TN (TT*NB)
#define TNH ((size_t)TN*HH)
#define NH (NB*HH)

// Scratch (no cudaMalloc allowed)
__device__ float g_gi [(size_t)TN * H3];   // input-side gates, cell 1 (+ b_ih + b_hh[r,z])
__device__ float g_gip[(size_t)TN * H3];   // input-side gates, cell 2 (+ b_ih_p + b_hh_p[r,z])
__device__ float g_A1 [2][NB * HH];        // masked hidden, cell 1, double-buffered by step parity
__device__ float g_A2 [2][NB * HH];        // masked hidden, cell 2

__device__ __forceinline__ unsigned f2tf(float x) {
    unsigned r;
    asm("cvt.rna.tf32.f32 %0, %1;" : "=r"(r) : "f"(x));
    return r;
}

__device__ __forceinline__ void mma8(float* c, const unsigned* a, const unsigned* b) {
    asm volatile(
        "mma.sync.aligned.m16n8k8.row.col.f32.tf32.tf32.f32 "
        "{%0,%1,%2,%3},{%4,%5,%6,%7},{%8,%9},{%0,%1,%2,%3};"
        : "+f"(c[0]), "+f"(c[1]), "+f"(c[2]), "+f"(c[3])
        : "r"(a[0]), "r"(a[1]), "r"(a[2]), "r"(a[3]), "r"(b[0]), "r"(b[1]));
}

__device__ __forceinline__ float fsig(float x) {
    return 1.f / (1.f + __expf(-x));
}
__device__ __forceinline__ float ftanh(float x) {
    return 1.f - 2.f / (__expf(2.f * x) + 1.f);
}

// ===========================================================================
// GI GEMM: g_gi  = [x, ma] @ w_ih^T   + b_ih  + [b_hh  (r,z only)]
//          g_gip =      ma @ w_ih_p^T + b_ih_p + [b_hh_p (r,z only)]
// C is 32768 x 1536. Main K=512 (x part), tail K=8 (masked action).
// ===========================================================================
__global__ void __launch_bounds__(256) gi_gemm_k(
    const float* __restrict__ x,
    const float* __restrict__ wih,  const float* __restrict__ wihp,
    const float* __restrict__ pah,  const float* __restrict__ masks,
    const float* __restrict__ bih,  const float* __restrict__ bihp,
    const float* __restrict__ bhh,  const float* __restrict__ bhhp)
{
    constexpr int BM = 128, BN = 128, BK = 16, SA = 20;
    constexpr int WRM = 2, WRN = 4;
    constexpr int MT = BM / (WRM * 16);   // 4
    constexpr int NT = BN / (WRN * 8);    // 4
    constexpr int AV = BM * BK / 4 / 256; // 2
    constexpr int BV = BN * BK / 4 / 256; // 2

    __shared__ unsigned sA[2][BM * SA];
    __shared__ unsigned sB[2][BN * SA];

    const int m0 = blockIdx.y * BM;
    const int n0 = blockIdx.x * BN;
    const float* Bg = wih + (size_t)n0 * 520;

    const int tid = threadIdx.x, lane = tid & 31, warp = tid >> 5;
    const int wm = warp % WRM, wn = warp / WRM;

    float acc[MT][NT][4];
    float acc2[MT][NT][4];
#pragma unroll
    for (int i = 0; i < MT; i++)
#pragma unroll
        for (int j = 0; j < NT; j++)
#pragma unroll
            for (int q = 0; q < 4; q++) { acc[i][j][q] = 0.f; acc2[i][j][q] = 0.f; }

    unsigned ra[AV][4], rb[BV][4];

    auto GL = [&](int kc) {
#pragma unroll
        for (int i = 0; i < AV; i++) {
            int s = tid + i * 256; int r = s >> 2; int c = (s & 3) << 2;
            float4 v = *reinterpret_cast<const float4*>(x + (size_t)(m0 + r) * EE + kc * BK + c);
            ra[i][0] = f2tf(v.x); ra[i][1] = f2tf(v.y); ra[i][2] = f2tf(v.z); ra[i][3] = f2tf(v.w);
        }
#pragma unroll
        for (int i = 0; i < BV; i++) {
            int s = tid + i * 256; int r = s >> 2; int c = (s & 3) << 2;
            float4 v = *reinterpret_cast<const float4*>(Bg + (size_t)r * 520 + kc * BK + c);
            rb[i][0] = f2tf(v.x); rb[i][1] = f2tf(v.y); rb[i][2] = f2tf(v.z); rb[i][3] = f2tf(v.w);
        }
    };
    auto SS = [&](int buf) {
#pragma unroll
        for (int i = 0; i < AV; i++) {
            int s = tid + i * 256; int r = s >> 2; int c = (s & 3) << 2;
            *reinterpret_cast<uint4*>(&sA[buf][r * SA + c]) = *reinterpret_cast<uint4*>(ra[i]);
        }
#pragma unroll
        for (int i = 0; i < BV; i++) {
            int s = tid + i * 256; int r = s >> 2; int c = (s & 3) << 2;
            *reinterpret_cast<uint4*>(&sB[buf][r * SA + c]) = *reinterpret_cast<uint4*>(rb[i]);
        }
    };
    auto COMP = [&](int buf) {
#pragma unroll
        for (int k8 = 0; k8 < BK / 8; k8++) {
            unsigned af[MT][4]; unsigned bf[NT][2];
#pragma unroll
            for (int mt = 0; mt < MT; mt++) {
                int r = wm * MT * 16 + mt * 16 + (lane >> 2);
                int c = k8 * 8 + (lane & 3);
                af[mt][0] = sA[buf][r * SA + c];
                af[mt][1] = sA[buf][(r + 8) * SA + c];
                af[mt][2] = sA[buf][r * SA + c + 4];
                af[mt][3] = sA[buf][(r + 8) * SA + c + 4];
            }
#pragma unroll
            for (int nt = 0; nt < NT; nt++) {
                int n = wn * NT * 8 + nt * 8 + (lane >> 2);
                int kk = k8 * 8 + (lane & 3);
                bf[nt][0] = sB[buf][n * SA + kk];
                bf[nt][1] = sB[buf][n * SA + kk + 4];
            }
#pragma unroll
            for (int mt = 0; mt < MT; mt++)
#pragma unroll
                for (int nt = 0; nt < NT; nt++)
                    mma8(acc[mt][nt], af[mt], bf[nt]);
        }
    };

    GL(0); SS(0); __syncthreads();
    constexpr int NKC = EE / BK;
    for (int kc = 0; kc < NKC; kc++) {
        if (kc + 1 < NKC) GL(kc + 1);
        COMP(kc & 1);
        if (kc + 1 < NKC) SS((kc + 1) & 1);
        __syncthreads();
    }

    // Tail: masked prev-action (K=8) vs w_ih[:,512:520] into acc, vs w_ih_p into acc2.
    {
        int s = tid;
        if (s < BM * 2) {
            int r = s >> 1; int c = (s & 1) << 2;
            float4 v = *reinterpret_cast<const float4*>(pah + (size_t)(m0 + r) * AD + c);
            float mk = masks[m0 + r];
            uint4 t4 = { f2tf(v.x * mk), f2tf(v.y * mk), f2tf(v.z * mk), f2tf(v.w * mk) };
            *reinterpret_cast<uint4*>(&sA[0][r * SA + c]) = t4;
        }
        if (s < BN * 2) {
            int n = s >> 1; int c = (s & 1) << 2;
            float4 v = *reinterpret_cast<const float4*>(wih + (size_t)(n0 + n) * 520 + 512 + c);
            uint4 t4 = { f2tf(v.x), f2tf(v.y), f2tf(v.z), f2tf(v.w) };
            *reinterpret_cast<uint4*>(&sB[0][n * SA + c]) = t4;
            float4 w = *reinterpret_cast<const float4*>(wihp + (size_t)(n0 + n) * AD + c);
            uint4 t5 = { f2tf(w.x), f2tf(w.y), f2tf(w.z), f2tf(w.w) };
            *reinterpret_cast<uint4*>(&sB[1][n * SA + c]) = t5;
        }
    }
    __syncthreads();
    {
        unsigned af2[MT][4], b0f[NT][2], b1f[NT][2];
#pragma unroll
        for (int mt = 0; mt < MT; mt++) {
            int r = wm * MT * 16 + mt * 16 + (lane >> 2);
            int c = (lane & 3);
            af2[mt][0] = sA[0][r * SA + c];
            af2[mt][1] = sA[0][(r + 8) * SA + c];
            af2[mt][2] = sA[0][r * SA + c + 4];
            af2[mt][3] = sA[0][(r + 8) * SA + c + 4];
        }
#pragma unroll
        for (int nt = 0; nt < NT; nt++) {
            int n = wn * NT * 8 + nt * 8 + (lane >> 2);
            int kk = (lane & 3);
            b0f[nt][0] = sB[0][n * SA + kk]; b0f[nt][1] = sB[0][n * SA + kk + 4];
            b1f[nt][0] = sB[1][n * SA + kk]; b1f[nt][1] = sB[1][n * SA + kk + 4];
        }
#pragma unroll
        for (int mt = 0; mt < MT; mt++)
#pragma unroll
            for (int nt = 0; nt < NT; nt++) {
                mma8(acc[mt][nt], af2[mt], b0f[nt]);
                mma8(acc2[mt][nt], af2[mt], b1f[nt]);
            }
    }

    // Epilogue: add biases (b_hh only folded for r,z gates; n-gate bias applied later)
#pragma unroll
    for (int mt = 0; mt < MT; mt++)
#pragma unroll
        for (int nt = 0; nt < NT; nt++) {
            int r = m0 + wm * MT * 16 + mt * 16 + (lane >> 2);
            int c = n0 + wn * NT * 8 + nt * 8 + ((lane & 3) << 1);
            float hb0 = (c < 1024) ? bhh[c] : 0.f;
            float hb1 = (c < 1024) ? bhh[c + 1] : 0.f;
            float b0 = bih[c] + hb0, b1 = bih[c + 1] + hb1;
            *reinterpret_cast<float2*>(&g_gi[(size_t)r * H3 + c]) =
                make_float2(acc[mt][nt][0] + b0, acc[mt][nt][1] + b1);
            *reinterpret_cast<float2*>(&g_gi[(size_t)(r + 8) * H3 + c]) =
                make_float2(acc[mt][nt][2] + b0, acc[mt][nt][3] + b1);
            float pb0 = (c < 1024) ? bhhp[c] : 0.f;
            float pb1 = (c < 1024) ? bhhp[c + 1] : 0.f;
            float p0 = bihp[c] + pb0, p1 = bihp[c + 1] + pb1;
            *reinterpret_cast<float2*>(&g_gip[(size_t)r * H3 + c]) =
                make_float2(acc2[mt][nt][0] + p0, acc2[mt][nt][1] + p1);
            *reinterpret_cast<float2*>(&g_gip[(size_t)(r + 8) * H3 + c]) =
                make_float2(acc2[mt][nt][2] + p0, acc2[mt][nt][3] + p1);
        }
}

// ===========================================================================
// Fused recurrent step: GEMM (all 3 gates per tile) + gate math + state update.
// grid = (16 j-tiles, 4 m-tiles, 2 cells); block = 256.
// Each CTA: rows m0..m0+63 (batch), cols j0..j0+31 (hidden), gates r/z/n.
// Reads A[t&1], writes A[(t+1)&1] (double-buffered to avoid intra-step races).
// ===========================================================================
__global__ void __launch_bounds__(256) step_k(
    int t,
    const float* __restrict__ whh, const float* __restrict__ whhp,
    const float* __restrict__ masks, const float* __restrict__ ginit,
    const float* __restrict__ bhh, const float* __restrict__ bhhp,
    float* __restrict__ out)
{
    constexpr int BK = 16, SA = 20;
    __shared__ unsigned sA[2][64 * SA];
    __shared__ unsigned sB[2][96 * SA];

    const int cell = blockIdx.z;
    const int m0 = blockIdx.y * 64;
    const int j0 = blockIdx.x * 32;
    const float* W   = cell ? whhp : whh;
    const float* Ard = cell ? g_A2[t & 1] : g_A1[t & 1];
    float*       Awr = cell ? g_A2[(t + 1) & 1] : g_A1[(t + 1) & 1];

    const int tid = threadIdx.x, lane = tid & 31, warp = tid >> 5;
    const int wm = warp & 3, wn = warp >> 2;

    float acc[3][2][4];
#pragma unroll
    for (int g = 0; g < 3; g++)
#pragma unroll
        for (int nt = 0; nt < 2; nt++)
#pragma unroll
            for (int q = 0; q < 4; q++) acc[g][nt][q] = 0.f;

    // A: 64x16 floats = 256 float4 (1/thread). B: 96x16 = 384 float4 (pass 2 predicated).
    const int ar = tid >> 2, ac = (tid & 3) << 2;
    unsigned ra[4], rb[2][4];
    const bool bp2 = tid < 128;

    auto GL = [&](int kc) {
        float4 v = *reinterpret_cast<const float4*>(Ard + (size_t)(m0 + ar) * HH + kc * BK + ac);
        ra[0] = f2tf(v.x); ra[1] = f2tf(v.y); ra[2] = f2tf(v.z); ra[3] = f2tf(v.w);
#pragma unroll
        for (int i = 0; i < 2; i++) {
            int s = tid + i * 256;
            if (i == 0 || bp2) {
                int br = s >> 2; int bc = (s & 3) << 2;
                int g = br >> 5, jj = br & 31;
                float4 w = *reinterpret_cast<const float4*>(
                    W + (size_t)(g * HH + j0 + jj) * HH + kc * BK + bc);
                rb[i][0] = f2tf(w.x); rb[i][1] = f2tf(w.y); rb[i][2] = f2tf(w.z); rb[i][3] = f2tf(w.w);
            }
        }
    };
    auto SS = [&](int buf) {
        *reinterpret_cast<uint4*>(&sA[buf][ar * SA + ac]) = *reinterpret_cast<uint4*>(ra);
#pragma unroll
        for (int i = 0; i < 2; i++) {
            int s = tid + i * 256;
            if (i == 0 || bp2) {
                int br = s >> 2; int bc = (s & 3) << 2;
                *reinterpret_cast<uint4*>(&sB[buf][br * SA + bc]) = *reinterpret_cast<uint4*>(rb[i]);
            }
        }
    };
    auto COMP = [&](int buf) {
#pragma unroll
        for (int k8 = 0; k8 < 2; k8++) {
            unsigned af[4];
            int r = wm * 16 + (lane >> 2);
            int ck = k8 * 8 + (lane & 3);
            af[0] = sA[buf][r * SA + ck];
            af[1] = sA[buf][(r + 8) * SA + ck];
            af[2] = sA[buf][r * SA + ck + 4];
            af[3] = sA[buf][(r + 8) * SA + ck + 4];
#pragma unroll
            for (int g = 0; g < 3; g++)
#pragma unroll
                for (int nt = 0; nt < 2; nt++) {
                    int bn = g * 32 + wn * 16 + nt * 8 + (lane >> 2);
                    unsigned bf[2] = { sB[buf][bn * SA + ck], sB[buf][bn * SA + ck + 4] };
                    mma8(acc[g][nt], af, bf);
                }
        }
    };

    GL(0); SS(0); __syncthreads();
    constexpr int NKC = HH / BK;   // 32
    for (int kc = 0; kc < NKC; kc++) {
        if (kc + 1 < NKC) GL(kc + 1);
        COMP(kc & 1);
        if (kc + 1 < NKC) SS((kc + 1) & 1);
        __syncthreads();
    }

    // ---- Fused gate epilogue ----
    const float* gi = cell ? g_gip : g_gi;
    const float* bh = cell ? bhhp : bhh;
    float* outs = out + (cell ? (TNH + NH) : 0);
    float* hf   = out + (cell ? (2 * TNH + NH) : TNH);

    const int rbase = m0 + wm * 16 + (lane >> 2);
    const int cbase = j0 + wn * 16 + ((lane & 3) << 1);

#pragma unroll
    for (int half = 0; half < 2; half++) {
        const int n = rbase + half * 8;
        const size_t mrow = (size_t)t * NB + n;
        float mnx = 0.f;
        if (t < TT - 1) mnx = masks[(size_t)(t + 1) * NB + n];
#pragma unroll
        for (int nt = 0; nt < 2; nt++) {
            const int c = cbase + nt * 8;
            const size_t gb = mrow * H3 + c;
            float2 ir = *reinterpret_cast<const float2*>(gi + gb);
            float2 iz = *reinterpret_cast<const float2*>(gi + gb + HH);
            float2 in = *reinterpret_cast<const float2*>(gi + gb + 2 * HH);
            float2 bn2 = *reinterpret_cast<const float2*>(bh + 2 * HH + c);
            float2 hp = *reinterpret_cast<const float2*>(Ard + (size_t)n * HH + c);

            float r0 = fsig(ir.x + acc[0][nt][half * 2]);
            float r1 = fsig(ir.y + acc[0][nt][half * 2 + 1]);
            float z0 = fsig(iz.x + acc[1][nt][half * 2]);
            float z1 = fsig(iz.y + acc[1][nt][half * 2 + 1]);
            float n0 = ftanh(in.x + r0 * (acc[2][nt][half * 2] + bn2.x));
            float n1 = ftanh(in.y + r1 * (acc[2][nt][half * 2 + 1] + bn2.y));
            float h0 = (1.f - z0) * n0 + z0 * hp.x;
            float h1 = (1.f - z1) * n1 + z1 * hp.y;

            *reinterpret_cast<float2*>(outs + mrow * HH + c) = make_float2(h0, h1);

            if (t == TT - 1) {
                *reinterpret_cast<float2*>(hf + (size_t)n * HH + c) = make_float2(h0, h1);
            } else {
                float a0 = h0 * mnx, a1 = h1 * mnx;
                if (cell) {
                    float2 gv = *reinterpret_cast<const float2*>(
                        ginit + ((size_t)(t + 1) * NB + n) * HH + c);
                    a0 += gv.x * (1.f - mnx);
                    a1 += gv.y * (1.f - mnx);
                }
                *reinterpret_cast<float2*>(Awr + (size_t)n * HH + c) = make_float2(a0, a1);
            }
        }
    }
}

__global__ void init_k(const float* __restrict__ hxs, const float* __restrict__ hys,
                       const float* __restrict__ masks, const float* __restrict__ ginit)
{
    int idx = blockIdx.x * blockDim.x + threadIdx.x;
    int cell = idx >> 17;
    int e = idx & (NH - 1);
    int n = e >> 9;
    float m0 = masks[n];
    if (!cell) g_A1[0][e] = hxs[e] * m0;
    else       g_A2[0][e] = hys[e] * m0 + ginit[e] * (1.f - m0);
}

extern "C" void kernel_launch(void* const* d_in, const int* in_sizes, int n_in,
                              void* d_out, int out_size)
{
    const float* x     = (const float*)d_in[0];
    const float* hxs   = (const float*)d_in[1];
    const float* hys   = (const float*)d_in[2];
    const float* ginit = (const float*)d_in[3];
    const float* masks = (const float*)d_in[4];
    const float* pah   = (const float*)d_in[5];
    const float* wih   = (const float*)d_in[6];
    const float* whh   = (const float*)d_in[7];
    const float* bih   = (const float*)d_in[8];
    const float* bhh   = (const float*)d_in[9];
    const float* wihp  = (const float*)d_in[10];
    const float* whhp  = (const float*)d_in[11];
    const float* bihp  = (const float*)d_in[12];
    const float* bhhp  = (const float*)d_in[13];
    float* out = (float*)d_out;

    init_k<<<1024, 256>>>(hxs, hys, masks, ginit);

    gi_gemm_k<<<dim3(12, 256), 256>>>(x, wih, wihp, pah, masks, bih, bihp, bhh, bhhp);

    for (int t = 0; t < TT; t++) {
        step_k<<<dim3(16, 4, 2), 256>>>(t, whh, whhp, masks, ginit, bhh, bhhp, out);
    }
}

// round 3
// speedup vs baseline: 1.7117x; 1.5744x over previous
#include <cuda_runtime.h>
#include <math.h>

#define TT 128
#define NB 256
#define EE 512
#define AD 8
#define HH 512
#define H3 1536
#define TN (TT*NB)
#define TNH ((size_t)TN*HH)
#define NH (NB*HH)
#define NCTA 128

// Scratch (no cudaMalloc allowed)
__device__ float g_gi [(size_t)TN * H3];   // input-side gates, cell 1 (+ b_ih + b_hh[r,z])
__device__ float g_gip[(size_t)TN * H3];   // input-side gates, cell 2
__device__ float g_A1 [2][NB * HH];        // masked hidden, cell 1, parity double-buffer
__device__ float g_A2 [2][NB * HH];        // masked hidden, cell 2
__device__ unsigned g_count;               // grid barrier
__device__ unsigned g_gen;

__device__ __forceinline__ unsigned f2tf(float x) {
    unsigned r;
    asm("cvt.rna.tf32.f32 %0, %1;" : "=r"(r) : "f"(x));
    return r;
}

__device__ __forceinline__ void mma8(float* c, const unsigned* a, const unsigned* b) {
    asm volatile(
        "mma.sync.aligned.m16n8k8.row.col.f32.tf32.tf32.f32 "
        "{%0,%1,%2,%3},{%4,%5,%6,%7},{%8,%9},{%0,%1,%2,%3};"
        : "+f"(c[0]), "+f"(c[1]), "+f"(c[2]), "+f"(c[3])
        : "r"(a[0]), "r"(a[1]), "r"(a[2]), "r"(a[3]), "r"(b[0]), "r"(b[1]));
}

__device__ __forceinline__ float fsig(float x) {
    return 1.f / (1.f + __expf(-x));
}
__device__ __forceinline__ float ftanh(float x) {
    return 1.f - 2.f / (__expf(2.f * x) + 1.f);
}

__device__ __forceinline__ float2 ldcg2(const float* p) {
    float2 v;
    asm volatile("ld.global.cg.v2.f32 {%0,%1}, [%2];" : "=f"(v.x), "=f"(v.y) : "l"(p));
    return v;
}

__device__ __forceinline__ void grid_bar() {
    __threadfence();
    __syncthreads();
    if (threadIdx.x == 0) {
        unsigned gen;
        asm volatile("ld.acquire.gpu.u32 %0, [%1];" : "=r"(gen) : "l"(&g_gen));
        unsigned v = atomicAdd(&g_count, 1u);
        if (v == NCTA - 1) {
            g_count = 0u;
            asm volatile("st.release.gpu.u32 [%0], %1;" :: "l"(&g_gen), "r"(gen + 1u));
        } else {
            unsigned cur;
            do {
                __nanosleep(32);
                asm volatile("ld.acquire.gpu.u32 %0, [%1];" : "=r"(cur) : "l"(&g_gen));
            } while (cur == gen);
        }
    }
    __syncthreads();
}

// ===========================================================================
// GI GEMM (unchanged from round 2, passing): g_gi/g_gip with biases folded
// ===========================================================================
__global__ void __launch_bounds__(256) gi_gemm_k(
    const float* __restrict__ x,
    const float* __restrict__ wih,  const float* __restrict__ wihp,
    const float* __restrict__ pah,  const float* __restrict__ masks,
    const float* __restrict__ bih,  const float* __restrict__ bihp,
    const float* __restrict__ bhh,  const float* __restrict__ bhhp)
{
    constexpr int BM = 128, BN = 128, BK = 16, SA = 20;
    constexpr int WRM = 2;
    constexpr int MT = 4, NT = 4, AV = 2, BV = 2;

    __shared__ unsigned sA[2][BM * SA];
    __shared__ unsigned sB[2][BN * SA];

    const int m0 = blockIdx.y * BM;
    const int n0 = blockIdx.x * BN;
    const float* Bg = wih + (size_t)n0 * 520;

    const int tid = threadIdx.x, lane = tid & 31, warp = tid >> 5;
    const int wm = warp % WRM, wn = warp / WRM;

    float acc[MT][NT][4];
    float acc2[MT][NT][4];
#pragma unroll
    for (int i = 0; i < MT; i++)
#pragma unroll
        for (int j = 0; j < NT; j++)
#pragma unroll
            for (int q = 0; q < 4; q++) { acc[i][j][q] = 0.f; acc2[i][j][q] = 0.f; }

    unsigned ra[AV][4], rb[BV][4];

    auto GL = [&](int kc) {
#pragma unroll
        for (int i = 0; i < AV; i++) {
            int s = tid + i * 256; int r = s >> 2; int c = (s & 3) << 2;
            float4 v = *reinterpret_cast<const float4*>(x + (size_t)(m0 + r) * EE + kc * BK + c);
            ra[i][0] = f2tf(v.x); ra[i][1] = f2tf(v.y); ra[i][2] = f2tf(v.z); ra[i][3] = f2tf(v.w);
        }
#pragma unroll
        for (int i = 0; i < BV; i++) {
            int s = tid + i * 256; int r = s >> 2; int c = (s & 3) << 2;
            float4 v = *reinterpret_cast<const float4*>(Bg + (size_t)r * 520 + kc * BK + c);
            rb[i][0] = f2tf(v.x); rb[i][1] = f2tf(v.y); rb[i][2] = f2tf(v.z); rb[i][3] = f2tf(v.w);
        }
    };
    auto SS = [&](int buf) {
#pragma unroll
        for (int i = 0; i < AV; i++) {
            int s = tid + i * 256; int r = s >> 2; int c = (s & 3) << 2;
            *reinterpret_cast<uint4*>(&sA[buf][r * SA + c]) = *reinterpret_cast<uint4*>(ra[i]);
        }
#pragma unroll
        for (int i = 0; i < BV; i++) {
            int s = tid + i * 256; int r = s >> 2; int c = (s & 3) << 2;
            *reinterpret_cast<uint4*>(&sB[buf][r * SA + c]) = *reinterpret_cast<uint4*>(rb[i]);
        }
    };
    auto COMP = [&](int buf) {
#pragma unroll
        for (int k8 = 0; k8 < BK / 8; k8++) {
            unsigned af[MT][4]; unsigned bf[NT][2];
#pragma unroll
            for (int mt = 0; mt < MT; mt++) {
                int r = wm * MT * 16 + mt * 16 + (lane >> 2);
                int c = k8 * 8 + (lane & 3);
                af[mt][0] = sA[buf][r * SA + c];
                af[mt][1] = sA[buf][(r + 8) * SA + c];
                af[mt][2] = sA[buf][r * SA + c + 4];
                af[mt][3] = sA[buf][(r + 8) * SA + c + 4];
            }
#pragma unroll
            for (int nt = 0; nt < NT; nt++) {
                int n = wn * NT * 8 + nt * 8 + (lane >> 2);
                int kk = k8 * 8 + (lane & 3);
                bf[nt][0] = sB[buf][n * SA + kk];
                bf[nt][1] = sB[buf][n * SA + kk + 4];
            }
#pragma unroll
            for (int mt = 0; mt < MT; mt++)
#pragma unroll
                for (int nt = 0; nt < NT; nt++)
                    mma8(acc[mt][nt], af[mt], bf[nt]);
        }
    };

    GL(0); SS(0); __syncthreads();
    constexpr int NKC = EE / BK;
    for (int kc = 0; kc < NKC; kc++) {
        if (kc + 1 < NKC) GL(kc + 1);
        COMP(kc & 1);
        if (kc + 1 < NKC) SS((kc + 1) & 1);
        __syncthreads();
    }

    // Tail: masked prev-action (K=8)
    {
        int s = tid;
        if (s < BM * 2) {
            int r = s >> 1; int c = (s & 1) << 2;
            float4 v = *reinterpret_cast<const float4*>(pah + (size_t)(m0 + r) * AD + c);
            float mk = masks[m0 + r];
            uint4 t4 = { f2tf(v.x * mk), f2tf(v.y * mk), f2tf(v.z * mk), f2tf(v.w * mk) };
            *reinterpret_cast<uint4*>(&sA[0][r * SA + c]) = t4;
        }
        if (s < BN * 2) {
            int n = s >> 1; int c = (s & 1) << 2;
            float4 v = *reinterpret_cast<const float4*>(wih + (size_t)(n0 + n) * 520 + 512 + c);
            uint4 t4 = { f2tf(v.x), f2tf(v.y), f2tf(v.z), f2tf(v.w) };
            *reinterpret_cast<uint4*>(&sB[0][n * SA + c]) = t4;
            float4 w = *reinterpret_cast<const float4*>(wihp + (size_t)(n0 + n) * AD + c);
            uint4 t5 = { f2tf(w.x), f2tf(w.y), f2tf(w.z), f2tf(w.w) };
            *reinterpret_cast<uint4*>(&sB[1][n * SA + c]) = t5;
        }
    }
    __syncthreads();
    {
        unsigned af2[MT][4], b0f[NT][2], b1f[NT][2];
#pragma unroll
        for (int mt = 0; mt < MT; mt++) {
            int r = wm * MT * 16 + mt * 16 + (lane >> 2);
            int c = (lane & 3);
            af2[mt][0] = sA[0][r * SA + c];
            af2[mt][1] = sA[0][(r + 8) * SA + c];
            af2[mt][2] = sA[0][r * SA + c + 4];
            af2[mt][3] = sA[0][(r + 8) * SA + c + 4];
        }
#pragma unroll
        for (int nt = 0; nt < NT; nt++) {
            int n = wn * NT * 8 + nt * 8 + (lane >> 2);
            int kk = (lane & 3);
            b0f[nt][0] = sB[0][n * SA + kk]; b0f[nt][1] = sB[0][n * SA + kk + 4];
            b1f[nt][0] = sB[1][n * SA + kk]; b1f[nt][1] = sB[1][n * SA + kk + 4];
        }
#pragma unroll
        for (int mt = 0; mt < MT; mt++)
#pragma unroll
            for (int nt = 0; nt < NT; nt++) {
                mma8(acc[mt][nt], af2[mt], b0f[nt]);
                mma8(acc2[mt][nt], af2[mt], b1f[nt]);
            }
    }

#pragma unroll
    for (int mt = 0; mt < MT; mt++)
#pragma unroll
        for (int nt = 0; nt < NT; nt++) {
            int r = m0 + wm * MT * 16 + mt * 16 + (lane >> 2);
            int c = n0 + wn * NT * 8 + nt * 8 + ((lane & 3) << 1);
            float hb0 = (c < 1024) ? bhh[c] : 0.f;
            float hb1 = (c < 1024) ? bhh[c + 1] : 0.f;
            float b0 = bih[c] + hb0, b1 = bih[c + 1] + hb1;
            *reinterpret_cast<float2*>(&g_gi[(size_t)r * H3 + c]) =
                make_float2(acc[mt][nt][0] + b0, acc[mt][nt][1] + b1);
            *reinterpret_cast<float2*>(&g_gi[(size_t)(r + 8) * H3 + c]) =
                make_float2(acc[mt][nt][2] + b0, acc[mt][nt][3] + b1);
            float pb0 = (c < 1024) ? bhhp[c] : 0.f;
            float pb1 = (c < 1024) ? bhhp[c + 1] : 0.f;
            float p0 = bihp[c] + pb0, p1 = bihp[c + 1] + pb1;
            *reinterpret_cast<float2*>(&g_gip[(size_t)r * H3 + c]) =
                make_float2(acc2[mt][nt][0] + p0, acc2[mt][nt][1] + p1);
            *reinterpret_cast<float2*>(&g_gip[(size_t)(r + 8) * H3 + c]) =
                make_float2(acc2[mt][nt][2] + p0, acc2[mt][nt][3] + p1);
        }
}

// ===========================================================================
// Persistent scan kernel. 128 CTAs x 128 threads, 1 CTA/SM.
// CTA (j-tile 32 cols, m-tile 64 rows, cell). Weights (96x512 tf32) resident
// in SMEM for all 128 steps. Per step: cp.async A pipeline -> MMA -> fused
// gate epilogue -> grid barrier.
// ===========================================================================
#define SW_LD 516
#define SA_LD 20
#define SMEM_SCAN ((96*SW_LD + 4*64*SA_LD) * 4)

__global__ void __launch_bounds__(128, 1) scan_k(
    const float* __restrict__ whh, const float* __restrict__ whhp,
    const float* __restrict__ masks, const float* __restrict__ ginit,
    const float* __restrict__ bhh, const float* __restrict__ bhhp,
    float* __restrict__ out)
{
    extern __shared__ unsigned sh[];
    unsigned* sW = sh;                      // 96 x 516
    unsigned* sA = sh + 96 * SW_LD;         // 4 stages x 64 x 20

    const int bx = blockIdx.x;
    const int j0 = (bx & 15) * 32;
    const int m0 = ((bx >> 4) & 3) * 64;
    const int cell = bx >> 6;

    const float* W  = cell ? whhp : whh;
    const float* gi = cell ? g_gip : g_gi;
    const float* bh = cell ? bhhp : bhh;
    float* outs = out + (cell ? (TNH + NH) : 0);
    float* hf   = out + (cell ? (2 * TNH + NH) : TNH);
    float* Abuf0 = cell ? g_A2[0] : g_A1[0];
    float* Abuf1 = cell ? g_A2[1] : g_A1[1];

    const int tid = threadIdx.x, lane = tid & 31, wn = tid >> 5;

    // ---- preload weights into SMEM (tf32, RNA) ----
    for (int i = tid; i < 96 * 128; i += 128) {
        int rr = i >> 7, cc = (i & 127) << 2;
        int g = rr >> 5, jj = rr & 31;
        float4 v = *reinterpret_cast<const float4*>(W + (size_t)(g * HH + j0 + jj) * HH + cc);
        unsigned* d = &sW[rr * SW_LD + cc];
        d[0] = f2tf(v.x); d[1] = f2tf(v.y); d[2] = f2tf(v.z); d[3] = f2tf(v.w);
    }
    const int cb = j0 + wn * 8 + ((lane & 3) << 1);
    const float2 bn2 = *reinterpret_cast<const float2*>(bh + 2 * HH + cb);
    __syncthreads();

    unsigned sA_u32;
    asm("{ .reg .u64 t; cvta.to.shared.u64 t, %1; cvt.u32.u64 %0, t; }"
        : "=r"(sA_u32) : "l"(sA));

    const int r0c = tid >> 2;
    const int r1c = (tid + 128) >> 2;
    const int ccp = (tid & 3) << 2;

    for (int t = 0; t < TT; t++) {
        const float* Ard = (t & 1) ? Abuf1 : Abuf0;
        float* Awr = (t & 1) ? Abuf0 : Abuf1;
        const size_t trow = (size_t)t * NB;

        // ---- epilogue operand prefetch (overlaps with GEMM) ----
        float2 pir[8], piz[8], pin[8], php[8], pg[8];
#pragma unroll
        for (int q = 0; q < 8; q++) {
            int n = m0 + (q >> 1) * 16 + (lane >> 2) + (q & 1) * 8;
            size_t gb = (trow + n) * (size_t)H3 + cb;
            pir[q] = *reinterpret_cast<const float2*>(gi + gb);
            piz[q] = *reinterpret_cast<const float2*>(gi + gb + HH);
            pin[q] = *reinterpret_cast<const float2*>(gi + gb + 2 * HH);
            php[q] = ldcg2(Ard + (size_t)n * HH + cb);
            if (cell && t < TT - 1)
                pg[q] = *reinterpret_cast<const float2*>(
                    ginit + (trow + NB + n) * (size_t)HH + cb);
            else
                pg[q] = make_float2(0.f, 0.f);
        }

        float acc[3][4][4];
#pragma unroll
        for (int g = 0; g < 3; g++)
#pragma unroll
            for (int mt = 0; mt < 4; mt++)
#pragma unroll
                for (int q = 0; q < 4; q++) acc[g][mt][q] = 0.f;

        const float* As = Ard + (size_t)m0 * HH;
        auto issue = [&](int kc) {
            unsigned d0 = sA_u32 + ((((kc & 3) * 64 + r0c) * SA_LD + ccp) << 2);
            const float* s0 = As + (size_t)r0c * HH + kc * 16 + ccp;
            asm volatile("cp.async.cg.shared.global [%0], [%1], 16;" :: "r"(d0), "l"(s0));
            unsigned d1 = sA_u32 + ((((kc & 3) * 64 + r1c) * SA_LD + ccp) << 2);
            const float* s1 = As + (size_t)r1c * HH + kc * 16 + ccp;
            asm volatile("cp.async.cg.shared.global [%0], [%1], 16;" :: "r"(d1), "l"(s1));
        };
        issue(0); asm volatile("cp.async.commit_group;");
        issue(1); asm volatile("cp.async.commit_group;");
        issue(2); asm volatile("cp.async.commit_group;");

        for (int kc = 0; kc < 32; kc++) {
            asm volatile("cp.async.wait_group 2;");
            __syncthreads();
            if (kc < 29) issue(kc + 3);
            asm volatile("cp.async.commit_group;");
            const unsigned* sab = sA + (kc & 3) * 64 * SA_LD;
#pragma unroll
            for (int k8 = 0; k8 < 2; k8++) {
                const int ck = k8 * 8 + (lane & 3);
                unsigned af[4][4];
#pragma unroll
                for (int mt = 0; mt < 4; mt++) {
                    int r = mt * 16 + (lane >> 2);
                    af[mt][0] = sab[r * SA_LD + ck];
                    af[mt][1] = sab[(r + 8) * SA_LD + ck];
                    af[mt][2] = sab[r * SA_LD + ck + 4];
                    af[mt][3] = sab[(r + 8) * SA_LD + ck + 4];
                }
                const int kg = kc * 16 + ck;
#pragma unroll
                for (int g = 0; g < 3; g++) {
                    int bn = g * 32 + wn * 8 + (lane >> 2);
                    unsigned bf[2] = { sW[bn * SW_LD + kg], sW[bn * SW_LD + kg + 4] };
#pragma unroll
                    for (int mt = 0; mt < 4; mt++)
                        mma8(acc[g][mt], af[mt], bf);
                }
            }
        }

        // ---- fused gate epilogue ----
#pragma unroll
        for (int mt = 0; mt < 4; mt++)
#pragma unroll
            for (int half = 0; half < 2; half++) {
                int q = mt * 2 + half;
                int n = m0 + mt * 16 + (lane >> 2) + half * 8;
                size_t mrow = trow + n;
                float rr0 = fsig(pir[q].x + acc[0][mt][half * 2]);
                float rr1 = fsig(pir[q].y + acc[0][mt][half * 2 + 1]);
                float zz0 = fsig(piz[q].x + acc[1][mt][half * 2]);
                float zz1 = fsig(piz[q].y + acc[1][mt][half * 2 + 1]);
                float nn0 = ftanh(pin[q].x + rr0 * (acc[2][mt][half * 2] + bn2.x));
                float nn1 = ftanh(pin[q].y + rr1 * (acc[2][mt][half * 2 + 1] + bn2.y));
                float h0 = (1.f - zz0) * nn0 + zz0 * php[q].x;
                float h1 = (1.f - zz1) * nn1 + zz1 * php[q].y;
                *reinterpret_cast<float2*>(outs + mrow * HH + cb) = make_float2(h0, h1);
                if (t == TT - 1) {
                    *reinterpret_cast<float2*>(hf + (size_t)n * HH + cb) = make_float2(h0, h1);
                } else {
                    float mnx = masks[trow + NB + n];
                    float a0 = h0 * mnx + pg[q].x * (1.f - mnx);
                    float a1 = h1 * mnx + pg[q].y * (1.f - mnx);
                    *reinterpret_cast<float2*>(Awr + (size_t)n * HH + cb) = make_float2(a0, a1);
                }
            }

        if (t < TT - 1) grid_bar();
    }
}

__global__ void init_k(const float* __restrict__ hxs, const float* __restrict__ hys,
                       const float* __restrict__ masks, const float* __restrict__ ginit)
{
    int idx = blockIdx.x * blockDim.x + threadIdx.x;
    int cell = idx >> 17;
    int e = idx & (NH - 1);
    int n = e >> 9;
    float m0 = masks[n];
    if (!cell) g_A1[0][e] = hxs[e] * m0;
    else       g_A2[0][e] = hys[e] * m0 + ginit[e] * (1.f - m0);
}

extern "C" void kernel_launch(void* const* d_in, const int* in_sizes, int n_in,
                              void* d_out, int out_size)
{
    const float* x     = (const float*)d_in[0];
    const float* hxs   = (const float*)d_in[1];
    const float* hys   = (const float*)d_in[2];
    const float* ginit = (const float*)d_in[3];
    const float* masks = (const float*)d_in[4];
    const float* pah   = (const float*)d_in[5];
    const float* wih   = (const float*)d_in[6];
    const float* whh   = (const float*)d_in[7];
    const float* bih   = (const float*)d_in[8];
    const float* bhh   = (const float*)d_in[9];
    const float* wihp  = (const float*)d_in[10];
    const float* whhp  = (const float*)d_in[11];
    const float* bihp  = (const float*)d_in[12];
    const float* bhhp  = (const float*)d_in[13];
    float* out = (float*)d_out;

    init_k<<<1024, 256>>>(hxs, hys, masks, ginit);

    gi_gemm_k<<<dim3(12, 256), 256>>>(x, wih, wihp, pah, masks, bih, bihp, bhh, bhhp);

    cudaFuncSetAttribute(scan_k, cudaFuncAttributeMaxDynamicSharedMemorySize, SMEM_SCAN);
    scan_k<<<NCTA, 128, SMEM_SCAN>>>(whh, whhp, masks, ginit, bhh, bhhp, out);
}

// round 4
// speedup vs baseline: 1.9802x; 1.1569x over previous
#include <cuda_runtime.h>
#include <math.h>

#define TT 128
#define NB 256
#define EE 512
#define AD 8
#define HH 512
#define H3 1536
#define TN (TT*NB)
#define TNH ((size_t)TN*HH)
#define NH (NB*HH)
#define NCTA 128
#define NGROUP 8
#define GSIZE 16

// Scratch (no cudaMalloc allowed)
__device__ float g_gi [(size_t)TN * H3];   // input-side gates, cell 1 (+ b_ih + b_hh[r,z])
__device__ float g_gip[(size_t)TN * H3];   // input-side gates, cell 2
__device__ float g_A1 [2][NB * HH];        // masked hidden, cell 1, parity double-buffer
__device__ float g_A2 [2][NB * HH];        // masked hidden, cell 2
struct __align__(128) Bar { unsigned cnt; unsigned gen; unsigned pad[30]; };
__device__ Bar g_bars[NGROUP];

__device__ __forceinline__ unsigned f2tf(float x) {
    unsigned r;
    asm("cvt.rna.tf32.f32 %0, %1;" : "=r"(r) : "f"(x));
    return r;
}

__device__ __forceinline__ void mma8(float* c, const unsigned* a, const unsigned* b) {
    asm volatile(
        "mma.sync.aligned.m16n8k8.row.col.f32.tf32.tf32.f32 "
        "{%0,%1,%2,%3},{%4,%5,%6,%7},{%8,%9},{%0,%1,%2,%3};"
        : "+f"(c[0]), "+f"(c[1]), "+f"(c[2]), "+f"(c[3])
        : "r"(a[0]), "r"(a[1]), "r"(a[2]), "r"(a[3]), "r"(b[0]), "r"(b[1]));
}

__device__ __forceinline__ float fsig(float x) {
    return 1.f / (1.f + __expf(-x));
}
__device__ __forceinline__ float ftanh(float x) {
    return 1.f - 2.f / (__expf(2.f * x) + 1.f);
}

__device__ __forceinline__ float2 ldcg2(const float* p) {
    float2 v;
    asm volatile("ld.global.cg.v2.f32 {%0,%1}, [%2];" : "=f"(v.x), "=f"(v.y) : "l"(p));
    return v;
}

// 16-CTA group barrier (sense-reversing, per-group cache line)
__device__ __forceinline__ void grid_bar(int grp) {
    __threadfence();
    __syncthreads();
    if (threadIdx.x == 0) {
        unsigned* cnt = &g_bars[grp].cnt;
        unsigned* gen = &g_bars[grp].gen;
        unsigned g0;
        asm volatile("ld.acquire.gpu.u32 %0, [%1];" : "=r"(g0) : "l"(gen));
        unsigned v = atomicAdd(cnt, 1u);
        if (v == GSIZE - 1) {
            *cnt = 0u;
            asm volatile("st.release.gpu.u32 [%0], %1;" :: "l"(gen), "r"(g0 + 1u));
        } else {
            unsigned cur;
            do {
                __nanosleep(32);
                asm volatile("ld.acquire.gpu.u32 %0, [%1];" : "=r"(cur) : "l"(gen));
            } while (cur == g0);
        }
    }
    __syncthreads();
}

// ===========================================================================
// GI GEMM (unchanged, passing): g_gi/g_gip with biases folded
// ===========================================================================
__global__ void __launch_bounds__(256) gi_gemm_k(
    const float* __restrict__ x,
    const float* __restrict__ wih,  const float* __restrict__ wihp,
    const float* __restrict__ pah,  const float* __restrict__ masks,
    const float* __restrict__ bih,  const float* __restrict__ bihp,
    const float* __restrict__ bhh,  const float* __restrict__ bhhp)
{
    constexpr int BM = 128, BN = 128, BK = 16, SA = 20;
    constexpr int WRM = 2;
    constexpr int MT = 4, NT = 4, AV = 2, BV = 2;

    __shared__ unsigned sA[2][BM * SA];
    __shared__ unsigned sB[2][BN * SA];

    const int m0 = blockIdx.y * BM;
    const int n0 = blockIdx.x * BN;
    const float* Bg = wih + (size_t)n0 * 520;

    const int tid = threadIdx.x, lane = tid & 31, warp = tid >> 5;
    const int wm = warp % WRM, wn = warp / WRM;

    float acc[MT][NT][4];
    float acc2[MT][NT][4];
#pragma unroll
    for (int i = 0; i < MT; i++)
#pragma unroll
        for (int j = 0; j < NT; j++)
#pragma unroll
            for (int q = 0; q < 4; q++) { acc[i][j][q] = 0.f; acc2[i][j][q] = 0.f; }

    unsigned ra[AV][4], rb[BV][4];

    auto GL = [&](int kc) {
#pragma unroll
        for (int i = 0; i < AV; i++) {
            int s = tid + i * 256; int r = s >> 2; int c = (s & 3) << 2;
            float4 v = *reinterpret_cast<const float4*>(x + (size_t)(m0 + r) * EE + kc * BK + c);
            ra[i][0] = f2tf(v.x); ra[i][1] = f2tf(v.y); ra[i][2] = f2tf(v.z); ra[i][3] = f2tf(v.w);
        }
#pragma unroll
        for (int i = 0; i < BV; i++) {
            int s = tid + i * 256; int r = s >> 2; int c = (s & 3) << 2;
            float4 v = *reinterpret_cast<const float4*>(Bg + (size_t)r * 520 + kc * BK + c);
            rb[i][0] = f2tf(v.x); rb[i][1] = f2tf(v.y); rb[i][2] = f2tf(v.z); rb[i][3] = f2tf(v.w);
        }
    };
    auto SS = [&](int buf) {
#pragma unroll
        for (int i = 0; i < AV; i++) {
            int s = tid + i * 256; int r = s >> 2; int c = (s & 3) << 2;
            *reinterpret_cast<uint4*>(&sA[buf][r * SA + c]) = *reinterpret_cast<uint4*>(ra[i]);
        }
#pragma unroll
        for (int i = 0; i < BV; i++) {
            int s = tid + i * 256; int r = s >> 2; int c = (s & 3) << 2;
            *reinterpret_cast<uint4*>(&sB[buf][r * SA + c]) = *reinterpret_cast<uint4*>(rb[i]);
        }
    };
    auto COMP = [&](int buf) {
#pragma unroll
        for (int k8 = 0; k8 < BK / 8; k8++) {
            unsigned af[MT][4]; unsigned bf[NT][2];
#pragma unroll
            for (int mt = 0; mt < MT; mt++) {
                int r = wm * MT * 16 + mt * 16 + (lane >> 2);
                int c = k8 * 8 + (lane & 3);
                af[mt][0] = sA[buf][r * SA + c];
                af[mt][1] = sA[buf][(r + 8) * SA + c];
                af[mt][2] = sA[buf][r * SA + c + 4];
                af[mt][3] = sA[buf][(r + 8) * SA + c + 4];
            }
#pragma unroll
            for (int nt = 0; nt < NT; nt++) {
                int n = wn * NT * 8 + nt * 8 + (lane >> 2);
                int kk = k8 * 8 + (lane & 3);
                bf[nt][0] = sB[buf][n * SA + kk];
                bf[nt][1] = sB[buf][n * SA + kk + 4];
            }
#pragma unroll
            for (int mt = 0; mt < MT; mt++)
#pragma unroll
                for (int nt = 0; nt < NT; nt++)
                    mma8(acc[mt][nt], af[mt], bf[nt]);
        }
    };

    GL(0); SS(0); __syncthreads();
    constexpr int NKC = EE / BK;
    for (int kc = 0; kc < NKC; kc++) {
        if (kc + 1 < NKC) GL(kc + 1);
        COMP(kc & 1);
        if (kc + 1 < NKC) SS((kc + 1) & 1);
        __syncthreads();
    }

    // Tail: masked prev-action (K=8)
    {
        int s = tid;
        if (s < BM * 2) {
            int r = s >> 1; int c = (s & 1) << 2;
            float4 v = *reinterpret_cast<const float4*>(pah + (size_t)(m0 + r) * AD + c);
            float mk = masks[m0 + r];
            uint4 t4 = { f2tf(v.x * mk), f2tf(v.y * mk), f2tf(v.z * mk), f2tf(v.w * mk) };
            *reinterpret_cast<uint4*>(&sA[0][r * SA + c]) = t4;
        }
        if (s < BN * 2) {
            int n = s >> 1; int c = (s & 1) << 2;
            float4 v = *reinterpret_cast<const float4*>(wih + (size_t)(n0 + n) * 520 + 512 + c);
            uint4 t4 = { f2tf(v.x), f2tf(v.y), f2tf(v.z), f2tf(v.w) };
            *reinterpret_cast<uint4*>(&sB[0][n * SA + c]) = t4;
            float4 w = *reinterpret_cast<const float4*>(wihp + (size_t)(n0 + n) * AD + c);
            uint4 t5 = { f2tf(w.x), f2tf(w.y), f2tf(w.z), f2tf(w.w) };
            *reinterpret_cast<uint4*>(&sB[1][n * SA + c]) = t5;
        }
    }
    __syncthreads();
    {
        unsigned af2[MT][4], b0f[NT][2], b1f[NT][2];
#pragma unroll
        for (int mt = 0; mt < MT; mt++) {
            int r = wm * MT * 16 + mt * 16 + (lane >> 2);
            int c = (lane & 3);
            af2[mt][0] = sA[0][r * SA + c];
            af2[mt][1] = sA[0][(r + 8) * SA + c];
            af2[mt][2] = sA[0][r * SA + c + 4];
            af2[mt][3] = sA[0][(r + 8) * SA + c + 4];
        }
#pragma unroll
        for (int nt = 0; nt < NT; nt++) {
            int n = wn * NT * 8 + nt * 8 + (lane >> 2);
            int kk = (lane & 3);
            b0f[nt][0] = sB[0][n * SA + kk]; b0f[nt][1] = sB[0][n * SA + kk + 4];
            b1f[nt][0] = sB[1][n * SA + kk]; b1f[nt][1] = sB[1][n * SA + kk + 4];
        }
#pragma unroll
        for (int mt = 0; mt < MT; mt++)
#pragma unroll
            for (int nt = 0; nt < NT; nt++) {
                mma8(acc[mt][nt], af2[mt], b0f[nt]);
                mma8(acc2[mt][nt], af2[mt], b1f[nt]);
            }
    }

#pragma unroll
    for (int mt = 0; mt < MT; mt++)
#pragma unroll
        for (int nt = 0; nt < NT; nt++) {
            int r = m0 + wm * MT * 16 + mt * 16 + (lane >> 2);
            int c = n0 + wn * NT * 8 + nt * 8 + ((lane & 3) << 1);
            float hb0 = (c < 1024) ? bhh[c] : 0.f;
            float hb1 = (c < 1024) ? bhh[c + 1] : 0.f;
            float b0 = bih[c] + hb0, b1 = bih[c + 1] + hb1;
            *reinterpret_cast<float2*>(&g_gi[(size_t)r * H3 + c]) =
                make_float2(acc[mt][nt][0] + b0, acc[mt][nt][1] + b1);
            *reinterpret_cast<float2*>(&g_gi[(size_t)(r + 8) * H3 + c]) =
                make_float2(acc[mt][nt][2] + b0, acc[mt][nt][3] + b1);
            float pb0 = (c < 1024) ? bhhp[c] : 0.f;
            float pb1 = (c < 1024) ? bhhp[c + 1] : 0.f;
            float p0 = bihp[c] + pb0, p1 = bihp[c + 1] + pb1;
            *reinterpret_cast<float2*>(&g_gip[(size_t)r * H3 + c]) =
                make_float2(acc2[mt][nt][0] + p0, acc2[mt][nt][1] + p1);
            *reinterpret_cast<float2*>(&g_gip[(size_t)(r + 8) * H3 + c]) =
                make_float2(acc2[mt][nt][2] + p0, acc2[mt][nt][3] + p1);
        }
}

// ===========================================================================
// Persistent scan kernel. 128 CTAs x 128 threads, 1 CTA/SM.
// (2,2) warp layout, BK=32, 3-stage cp.async, per-(m,cell)-group barriers.
// ===========================================================================
#define SW_LD 516
#define SA_LD 36
#define SMEM_SCAN ((96*SW_LD + 3*64*SA_LD) * 4)

__global__ void __launch_bounds__(128, 1) scan_k(
    const float* __restrict__ whh, const float* __restrict__ whhp,
    const float* __restrict__ masks, const float* __restrict__ ginit,
    const float* __restrict__ bhh, const float* __restrict__ bhhp,
    float* __restrict__ out)
{
    extern __shared__ unsigned sh[];
    unsigned* sW = sh;                      // 96 x 516
    unsigned* sA = sh + 96 * SW_LD;         // 3 stages x 64 x 36

    const int bx = blockIdx.x;
    const int j0 = (bx & 15) * 32;
    const int m0 = ((bx >> 4) & 3) * 64;
    const int cell = bx >> 6;
    const int grp = bx >> 4;                // (m,cell) group, 8 groups of 16

    const float* W  = cell ? whhp : whh;
    const float* gi = cell ? g_gip : g_gi;
    const float* bh = cell ? bhhp : bhh;
    float* outs = out + (cell ? (TNH + NH) : 0);
    float* hf   = out + (cell ? (2 * TNH + NH) : TNH);
    float* Abuf0 = cell ? g_A2[0] : g_A1[0];
    float* Abuf1 = cell ? g_A2[1] : g_A1[1];

    const int tid = threadIdx.x, lane = tid & 31, warp = tid >> 5;
    const int wm = warp & 1, wn = warp >> 1;

    // ---- preload weights into SMEM (tf32, RNA) ----
    for (int i = tid; i < 96 * 128; i += 128) {
        int rr = i >> 7, cc = (i & 127) << 2;
        int g = rr >> 5, jj = rr & 31;
        float4 v = *reinterpret_cast<const float4*>(W + (size_t)(g * HH + j0 + jj) * HH + cc);
        unsigned* d = &sW[rr * SW_LD + cc];
        d[0] = f2tf(v.x); d[1] = f2tf(v.y); d[2] = f2tf(v.z); d[3] = f2tf(v.w);
    }
    const int cb = j0 + wn * 16 + ((lane & 3) << 1);
    float2 bn2[2];
    bn2[0] = *reinterpret_cast<const float2*>(bh + 2 * HH + cb);
    bn2[1] = *reinterpret_cast<const float2*>(bh + 2 * HH + cb + 8);
    __syncthreads();

    unsigned sA_u32;
    asm("{ .reg .u64 t; cvta.to.shared.u64 t, %1; cvt.u32.u64 %0, t; }"
        : "=r"(sA_u32) : "l"(sA));

    for (int t = 0; t < TT; t++) {
        const float* Ard = (t & 1) ? Abuf1 : Abuf0;
        float* Awr = (t & 1) ? Abuf0 : Abuf1;
        const size_t trow = (size_t)t * NB;
        const float* As = Ard + (size_t)m0 * HH;

        // ---- cp.async pipeline prologue first (starts A loads ASAP) ----
        auto issue = [&](int kc, int stg) {
#pragma unroll
            for (int p = 0; p < 4; p++) {
                int s = tid + p * 128;
                int row = s >> 3;
                int c4 = (s & 7) << 2;
                unsigned d = sA_u32 + ((((stg * 64) + row) * SA_LD + c4) << 2);
                const float* src = As + (size_t)row * HH + kc * 32 + c4;
                asm volatile("cp.async.cg.shared.global [%0], [%1], 16;" :: "r"(d), "l"(src));
            }
        };
        issue(0, 0); asm volatile("cp.async.commit_group;");
        issue(1, 1); asm volatile("cp.async.commit_group;");

        // ---- epilogue operand prefetch (overlaps with GEMM) ----
        float2 pir[4][2], piz[4][2], pin[4][2], php[4][2], pg[4][2];
        float pmask[4];
#pragma unroll
        for (int q = 0; q < 4; q++) {
            int n = m0 + wm * 32 + (q >> 1) * 16 + (lane >> 2) + (q & 1) * 8;
            size_t gb = (trow + n) * (size_t)H3 + cb;
            if (t < TT - 1) pmask[q] = masks[trow + NB + n];
            else            pmask[q] = 0.f;
#pragma unroll
            for (int nt = 0; nt < 2; nt++) {
                pir[q][nt] = *reinterpret_cast<const float2*>(gi + gb + nt * 8);
                piz[q][nt] = *reinterpret_cast<const float2*>(gi + gb + HH + nt * 8);
                pin[q][nt] = *reinterpret_cast<const float2*>(gi + gb + 2 * HH + nt * 8);
                php[q][nt] = ldcg2(Ard + (size_t)n * HH + cb + nt * 8);
                if (cell && t < TT - 1)
                    pg[q][nt] = *reinterpret_cast<const float2*>(
                        ginit + (trow + NB + n) * (size_t)HH + cb + nt * 8);
                else
                    pg[q][nt] = make_float2(0.f, 0.f);
            }
        }

        float acc[3][2][2][4];
#pragma unroll
        for (int g = 0; g < 3; g++)
#pragma unroll
            for (int mt = 0; mt < 2; mt++)
#pragma unroll
                for (int nt = 0; nt < 2; nt++)
#pragma unroll
                    for (int q = 0; q < 4; q++) acc[g][mt][nt][q] = 0.f;

        int sr = 0;
        for (int kc = 0; kc < 16; kc++) {
            asm volatile("cp.async.wait_group 1;");
            __syncthreads();
            if (kc < 14) {
                int sw = sr + 2; if (sw >= 3) sw -= 3;
                issue(kc + 2, sw);
            }
            asm volatile("cp.async.commit_group;");
            const unsigned* sab = sA + sr * 64 * SA_LD;
#pragma unroll
            for (int k8 = 0; k8 < 4; k8++) {
                const int ck = k8 * 8 + (lane & 3);
                unsigned af[2][4];
#pragma unroll
                for (int mt = 0; mt < 2; mt++) {
                    int r = wm * 32 + mt * 16 + (lane >> 2);
                    af[mt][0] = sab[r * SA_LD + ck];
                    af[mt][1] = sab[(r + 8) * SA_LD + ck];
                    af[mt][2] = sab[r * SA_LD + ck + 4];
                    af[mt][3] = sab[(r + 8) * SA_LD + ck + 4];
                }
                const int kg = kc * 32 + ck;
#pragma unroll
                for (int g = 0; g < 3; g++)
#pragma unroll
                    for (int nt = 0; nt < 2; nt++) {
                        int bn = g * 32 + wn * 16 + nt * 8 + (lane >> 2);
                        unsigned bf[2] = { sW[bn * SW_LD + kg], sW[bn * SW_LD + kg + 4] };
#pragma unroll
                        for (int mt = 0; mt < 2; mt++)
                            mma8(acc[g][mt][nt], af[mt], bf);
                    }
            }
            sr++; if (sr >= 3) sr -= 3;
        }

        // ---- fused gate epilogue ----
#pragma unroll
        for (int mt = 0; mt < 2; mt++)
#pragma unroll
            for (int half = 0; half < 2; half++) {
                int q = mt * 2 + half;
                int n = m0 + wm * 32 + mt * 16 + (lane >> 2) + half * 8;
                size_t mrow = trow + n;
                float mnx = pmask[q];
#pragma unroll
                for (int nt = 0; nt < 2; nt++) {
                    int c = cb + nt * 8;
                    float rr0 = fsig(pir[q][nt].x + acc[0][mt][nt][half * 2]);
                    float rr1 = fsig(pir[q][nt].y + acc[0][mt][nt][half * 2 + 1]);
                    float zz0 = fsig(piz[q][nt].x + acc[1][mt][nt][half * 2]);
                    float zz1 = fsig(piz[q][nt].y + acc[1][mt][nt][half * 2 + 1]);
                    float nn0 = ftanh(pin[q][nt].x + rr0 * (acc[2][mt][nt][half * 2] + bn2[nt].x));
                    float nn1 = ftanh(pin[q][nt].y + rr1 * (acc[2][mt][nt][half * 2 + 1] + bn2[nt].y));
                    float h0 = (1.f - zz0) * nn0 + zz0 * php[q][nt].x;
                    float h1 = (1.f - zz1) * nn1 + zz1 * php[q][nt].y;
                    *reinterpret_cast<float2*>(outs + mrow * HH + c) = make_float2(h0, h1);
                    if (t == TT - 1) {
                        *reinterpret_cast<float2*>(hf + (size_t)n * HH + c) = make_float2(h0, h1);
                    } else {
                        float a0 = h0 * mnx + pg[q][nt].x * (1.f - mnx);
                        float a1 = h1 * mnx + pg[q][nt].y * (1.f - mnx);
                        *reinterpret_cast<float2*>(Awr + (size_t)n * HH + c) = make_float2(a0, a1);
                    }
                }
            }

        if (t < TT - 1) grid_bar(grp);
    }
}

__global__ void init_k(const float* __restrict__ hxs, const float* __restrict__ hys,
                       const float* __restrict__ masks, const float* __restrict__ ginit)
{
    int idx = blockIdx.x * blockDim.x + threadIdx.x;
    int cell = idx >> 17;
    int e = idx & (NH - 1);
    int n = e >> 9;
    float m0 = masks[n];
    if (!cell) g_A1[0][e] = hxs[e] * m0;
    else       g_A2[0][e] = hys[e] * m0 + ginit[e] * (1.f - m0);
}

extern "C" void kernel_launch(void* const* d_in, const int* in_sizes, int n_in,
                              void* d_out, int out_size)
{
    const float* x     = (const float*)d_in[0];
    const float* hxs   = (const float*)d_in[1];
    const float* hys   = (const float*)d_in[2];
    const float* ginit = (const float*)d_in[3];
    const float* masks = (const float*)d_in[4];
    const float* pah   = (const float*)d_in[5];
    const float* wih   = (const float*)d_in[6];
    const float* whh   = (const float*)d_in[7];
    const float* bih   = (const float*)d_in[8];
    const float* bhh   = (const float*)d_in[9];
    const float* wihp  = (const float*)d_in[10];
    const float* whhp  = (const float*)d_in[11];
    const float* bihp  = (const float*)d_in[12];
    const float* bhhp  = (const float*)d_in[13];
    float* out = (float*)d_out;

    init_k<<<1024, 256>>>(hxs, hys, masks, ginit);

    gi_gemm_k<<<dim3(12, 256), 256>>>(x, wih, wihp, pah, masks, bih, bihp, bhh, bhhp);

    cudaFuncSetAttribute(scan_k, cudaFuncAttributeMaxDynamicSharedMemorySize, SMEM_SCAN);
    scan_k<<<NCTA, 128, SMEM_SCAN>>>(whh, whhp, masks, ginit, bhh, bhhp, out);
}